// round 1
// baseline (speedup 1.0000x reference)
#include <cuda_runtime.h>

// ----------------------------------------------------------------------------
// Quaternion self-attention, n=4096 tokens, d=1024, fp32.
//   Q = x @ WQ^T ; K = x @ WK^T ; V = x @ WV^T        (torch Linear, no bias)
//   L_c = perm_c(Q) @ K^T   (signed block permutation, blocks of 256)
//   P_c = softmax_rows(L_c)
//   y[:, c*256:(c+1)*256] = P_c @ V[:, c*256:(c+1)*256]
//   w = P_3  (loop-leaked last component)
// Output: [ y (4096*1024) | w (4096*4096) ] fp32
// ----------------------------------------------------------------------------

#define NSEQ 4096
#define DIM  1024

// Scratch (device globals: allocation-free, graph-capture safe)
__device__ float g_Q [(size_t)NSEQ * DIM];
__device__ float g_K [(size_t)NSEQ * DIM];
__device__ float g_V [(size_t)NSEQ * DIM];
__device__ float g_Qp[(size_t)NSEQ * DIM];
__device__ float g_L [(size_t)NSEQ * NSEQ];

// Hamilton-product block permutation tables.
//   L_r: [ qr, -qx, -qy, -qz ]
//   L_i: [ qx,  qr, -qz,  qy ]
//   L_j: [ qy,  qz,  qr, -qx ]
//   L_k: [ qz, -qy,  qx,  qr ]
__constant__ int   c_src[4][4] = {{0,1,2,3},{1,0,3,2},{2,3,0,1},{3,2,1,0}};
__constant__ float c_sgn[4][4] = {{1.f,-1.f,-1.f,-1.f},
                                  {1.f, 1.f,-1.f, 1.f},
                                  {1.f, 1.f, 1.f,-1.f},
                                  {1.f,-1.f, 1.f, 1.f}};

// ----------------------------------------------------------------------------
// Generic 128x128 tile, 8x8-per-thread fp32 GEMM. Two operand layouts:
//   NT = true : C[i,j] = sum_k A[i,k] * B[j,k]   (A row-major MxK, B row-major NxK)
//   NT = false: C[i,j] = sum_k A[i,k] * B[k,j]   (A row-major MxK, B row-major KxN)
// All dims assumed multiples of the tile (true for every call here).
// ----------------------------------------------------------------------------
template <bool NT>
__global__ void __launch_bounds__(256)
gemm128(const float* __restrict__ A, const float* __restrict__ B,
        float* __restrict__ C, int K, int lda, int ldb, int ldc)
{
    __shared__ float As[8][128];
    __shared__ float Bs[8][128];

    const int tid = threadIdx.x;
    const int tx  = tid & 15;       // 0..15 -> N micro
    const int ty  = tid >> 4;       // 0..15 -> M micro
    const int m0  = blockIdx.y * 128;
    const int n0  = blockIdx.x * 128;

    const int arow = tid >> 1;          // 0..127
    const int ak4  = (tid & 1) * 4;     // 0 or 4
    const int brow = tid >> 5;          // 0..7   (NN path)
    const int bn4  = (tid & 31) * 4;    // 0..124 (NN path)

    float acc[8][8];
    #pragma unroll
    for (int i = 0; i < 8; i++)
        #pragma unroll
        for (int j = 0; j < 8; j++) acc[i][j] = 0.f;

    for (int k0 = 0; k0 < K; k0 += 8) {
        // A tile: 128 rows x 8 k, transposed into As[k][m]
        float4 av = *(const float4*)&A[(size_t)(m0 + arow) * lda + k0 + ak4];
        As[ak4 + 0][arow] = av.x;
        As[ak4 + 1][arow] = av.y;
        As[ak4 + 2][arow] = av.z;
        As[ak4 + 3][arow] = av.w;

        if (NT) {
            float4 bv = *(const float4*)&B[(size_t)(n0 + arow) * ldb + k0 + ak4];
            Bs[ak4 + 0][arow] = bv.x;
            Bs[ak4 + 1][arow] = bv.y;
            Bs[ak4 + 2][arow] = bv.z;
            Bs[ak4 + 3][arow] = bv.w;
        } else {
            float4 bv = *(const float4*)&B[(size_t)(k0 + brow) * ldb + n0 + bn4];
            *(float4*)&Bs[brow][bn4] = bv;
        }
        __syncthreads();

        #pragma unroll
        for (int k = 0; k < 8; k++) {
            float a[8], b[8];
            #pragma unroll
            for (int i = 0; i < 8; i++) a[i] = As[k][ty * 8 + i];
            #pragma unroll
            for (int j = 0; j < 8; j++) b[j] = Bs[k][tx * 8 + j];
            #pragma unroll
            for (int i = 0; i < 8; i++)
                #pragma unroll
                for (int j = 0; j < 8; j++)
                    acc[i][j] = fmaf(a[i], b[j], acc[i][j]);
        }
        __syncthreads();
    }

    #pragma unroll
    for (int i = 0; i < 8; i++) {
        float* cp = &C[(size_t)(m0 + ty * 8 + i) * ldc + n0 + tx * 8];
        float4 v0 = make_float4(acc[i][0], acc[i][1], acc[i][2], acc[i][3]);
        float4 v1 = make_float4(acc[i][4], acc[i][5], acc[i][6], acc[i][7]);
        *(float4*)cp       = v0;
        *((float4*)cp + 1) = v1;
    }
}

// ----------------------------------------------------------------------------
// Signed block permutation of Q for component c. One block per row; 256 threads,
// each handles one float4 per iteration (256 float4 per row).
// ----------------------------------------------------------------------------
__global__ void __launch_bounds__(256)
permute_q(const float* __restrict__ Q, float* __restrict__ Qp, int c)
{
    const int row  = blockIdx.x;
    const int col4 = threadIdx.x;        // 0..255 (float4 index in row)
    const int b    = col4 >> 6;          // which 256-wide block
    const int t4   = col4 & 63;
    const float s  = c_sgn[c][b];
    const int src  = c_src[c][b];

    float4 v = *(const float4*)&Q[(size_t)row * DIM + src * 256 + t4 * 4];
    float4 o = make_float4(s * v.x, s * v.y, s * v.z, s * v.w);
    *(float4*)&Qp[(size_t)row * DIM + col4 * 4] = o;
}

// ----------------------------------------------------------------------------
// Row softmax over 4096 columns, in-place; optionally mirrored to wout.
// One block (256 threads) per row; row cached in 16KB shared.
// ----------------------------------------------------------------------------
__global__ void __launch_bounds__(256)
softmax_row(float* __restrict__ L, float* __restrict__ wout)
{
    __shared__ float buf[NSEQ];
    __shared__ float red[8];

    const int row = blockIdx.x;
    float* Lr = L + (size_t)row * NSEQ;
    const int tid  = threadIdx.x;
    const int lane = tid & 31;
    const int wid  = tid >> 5;

    float lmax = -3.4e38f;
    #pragma unroll
    for (int it = 0; it < 4; it++) {
        int i = tid * 4 + it * 1024;
        float4 v = *(const float4*)&Lr[i];
        *(float4*)&buf[i] = v;
        lmax = fmaxf(lmax, fmaxf(fmaxf(v.x, v.y), fmaxf(v.z, v.w)));
    }
    #pragma unroll
    for (int o = 16; o; o >>= 1) lmax = fmaxf(lmax, __shfl_xor_sync(0xffffffffu, lmax, o));
    if (lane == 0) red[wid] = lmax;
    __syncthreads();
    if (tid == 0) {
        float m = red[0];
        #pragma unroll
        for (int w = 1; w < 8; w++) m = fmaxf(m, red[w]);
        red[0] = m;
    }
    __syncthreads();
    const float bmax = red[0];
    __syncthreads();   // protect red[] reuse

    float lsum = 0.f;
    #pragma unroll
    for (int it = 0; it < 4; it++) {
        int i = tid * 4 + it * 1024;
        float4 v = *(const float4*)&buf[i];
        v.x = __expf(v.x - bmax);
        v.y = __expf(v.y - bmax);
        v.z = __expf(v.z - bmax);
        v.w = __expf(v.w - bmax);
        *(float4*)&buf[i] = v;
        lsum += v.x + v.y + v.z + v.w;
    }
    #pragma unroll
    for (int o = 16; o; o >>= 1) lsum += __shfl_xor_sync(0xffffffffu, lsum, o);
    if (lane == 0) red[wid] = lsum;
    __syncthreads();
    if (tid == 0) {
        float s = 0.f;
        #pragma unroll
        for (int w = 0; w < 8; w++) s += red[w];
        red[0] = 1.f / s;
    }
    __syncthreads();
    const float inv = red[0];

    float* Wr = wout ? wout + (size_t)row * NSEQ : nullptr;
    #pragma unroll
    for (int it = 0; it < 4; it++) {
        int i = tid * 4 + it * 1024;
        float4 v = *(const float4*)&buf[i];
        v.x *= inv; v.y *= inv; v.z *= inv; v.w *= inv;
        *(float4*)&Lr[i] = v;
        if (Wr) *(float4*)&Wr[i] = v;
    }
}

// ----------------------------------------------------------------------------
// Launch
// ----------------------------------------------------------------------------
extern "C" void kernel_launch(void* const* d_in, const int* in_sizes, int n_in,
                              void* d_out, int out_size)
{
    const float* x  = (const float*)d_in[0];
    const float* WQ = (const float*)d_in[1];
    const float* WK = (const float*)d_in[2];
    const float* WV = (const float*)d_in[3];

    float* yout = (float*)d_out;                        // [4096,1024]
    float* wout = yout + (size_t)NSEQ * DIM;            // [4096,4096]

    float *Q, *K, *V, *Qp, *L;
    cudaGetSymbolAddress((void**)&Q,  g_Q);
    cudaGetSymbolAddress((void**)&K,  g_K);
    cudaGetSymbolAddress((void**)&V,  g_V);
    cudaGetSymbolAddress((void**)&Qp, g_Qp);
    cudaGetSymbolAddress((void**)&L,  g_L);

    dim3 blk(256);

    // QKV projections: [4096,1024] = x[4096,1024] @ W[1024,1024]^T  (NT)
    dim3 gProj(DIM / 128, NSEQ / 128);
    gemm128<true><<<gProj, blk>>>(x, WQ, Q, DIM, DIM, DIM, DIM);
    gemm128<true><<<gProj, blk>>>(x, WK, K, DIM, DIM, DIM, DIM);
    gemm128<true><<<gProj, blk>>>(x, WV, V, DIM, DIM, DIM, DIM);

    dim3 gLog(NSEQ / 128, NSEQ / 128);   // 32x32
    dim3 gOut(256 / 128, NSEQ / 128);    // 2x32

    for (int c = 0; c < 4; c++) {
        // Qp = signed block-permutation of Q
        permute_q<<<NSEQ, blk>>>(Q, Qp, c);
        // L = Qp @ K^T : [4096,4096], K-depth 1024  (NT)
        gemm128<true><<<gLog, blk>>>(Qp, K, L, DIM, DIM, DIM, NSEQ);
        // P = softmax_rows(L) in place; component 3 also exported as w
        softmax_row<<<NSEQ, blk>>>(L, (c == 3) ? wout : nullptr);
        // y[:, c*256 : (c+1)*256] = P @ V[:, c*256 : (c+1)*256]   (NN)
        gemm128<false><<<gOut, blk>>>(L, V + c * 256, yout + c * 256,
                                      NSEQ, NSEQ, DIM, DIM);
    }
}

// round 3
// speedup vs baseline: 4.2461x; 4.2461x over previous
#include <cuda_runtime.h>
#include <cuda_bf16.h>
#include <cstdint>

// ============================================================================
// Quaternion self-attention, n=4096, d=1024, fp32 in/out.
// GEMMs via Ampere-path tensor cores (mma.sync bf16, valid on plain sm_100):
// bf16 hi/lo 3-term split (AhBh + AhBl + AlBh) for ~fp32 accuracy.
//   Q,K,V = x @ W^T
//   L_c   = perm_c(Q) @ K^T   (perm folded into k-block coords + negated-Q copy)
//   P_c   = softmax_rows(L_c) (stored bf16 hi/lo; c==3 also writes w fp32)
//   y_c   = P_c @ V_c         (batched over c in one launch, B = V^T)
// Output: [ y (4096*1024) | w (4096*4096) ] fp32
// ============================================================================

#define NSEQ 4096
#define DIM  1024
#define NN   ((size_t)NSEQ * NSEQ)

// ---------------- scratch (device globals: allocation-free) ----------------
__device__ float g_Q[(size_t)NSEQ * DIM];
__device__ float g_K[(size_t)NSEQ * DIM];
__device__ float g_V[(size_t)NSEQ * DIM];
__device__ float g_L[NN];

__device__ __nv_bfloat16 g_xh[(size_t)NSEQ * DIM],  g_xl[(size_t)NSEQ * DIM];
__device__ __nv_bfloat16 g_Wh[3][(size_t)DIM * DIM], g_Wl[3][(size_t)DIM * DIM];
__device__ __nv_bfloat16 g_Qh[(size_t)NSEQ * DIM],  g_Ql[(size_t)NSEQ * DIM];
__device__ __nv_bfloat16 g_Qnh[(size_t)NSEQ * DIM], g_Qnl[(size_t)NSEQ * DIM];
__device__ __nv_bfloat16 g_Kh[(size_t)NSEQ * DIM],  g_Kl[(size_t)NSEQ * DIM];
__device__ __nv_bfloat16 g_Vth[(size_t)DIM * NSEQ], g_Vtl[(size_t)DIM * NSEQ];
__device__ __nv_bfloat16 g_Ph[4 * NN], g_Pl[4 * NN];

// Hamilton-product permutation: Qp_c[:, b*256+o] = sgn * Q[:, src*256+o]
__constant__ int c_src[4][4] = {{0,1,2,3},{1,0,3,2},{2,3,0,1},{3,2,1,0}};
__constant__ int c_neg[4][4] = {{0,1,1,1},{0,0,1,0},{0,0,0,1},{0,1,0,0}};

// ---------------------------- PTX helpers ----------------------------------
__device__ __forceinline__ uint32_t smem_u32(const void* p) {
    uint32_t a;
    asm("{ .reg .u64 t; cvta.to.shared.u64 t, %1; cvt.u32.u64 %0, t; }" : "=r"(a) : "l"(p));
    return a;
}

#define CPASYNC16(dst, src) \
    asm volatile("cp.async.cg.shared.global [%0], [%1], 16;" :: "r"(dst), "l"(src))
#define CPCOMMIT() asm volatile("cp.async.commit_group;" ::: "memory")
#define CPWAIT2()  asm volatile("cp.async.wait_group 2;" ::: "memory")

#define LDSM4(r, addr) \
    asm volatile("ldmatrix.sync.aligned.m8n8.x4.shared.b16 {%0,%1,%2,%3}, [%4];" \
        : "=r"((r)[0]), "=r"((r)[1]), "=r"((r)[2]), "=r"((r)[3]) : "r"(addr))

#define MMA_BF16(d, a, b0, b1) \
    asm volatile("mma.sync.aligned.m16n8k16.row.col.f32.bf16.bf16.f32 " \
        "{%0,%1,%2,%3}, {%4,%5,%6,%7}, {%8,%9}, {%0,%1,%2,%3};" \
        : "+f"((d)[0]), "+f"((d)[1]), "+f"((d)[2]), "+f"((d)[3]) \
        : "r"((a)[0]), "r"((a)[1]), "r"((a)[2]), "r"((a)[3]), "r"(b0), "r"(b1))

// ---------------------------- tiling constants -----------------------------
// CTA tile 128x128, k-chunk 64 (bf16 -> 128B rows, Swizzle<3,4,3>).
// Stage = Ah|Al|Bh|Bl, 16KB each = 64KB. 3 stages.
#define TILE_B     16384
#define STAGE_B    65536
#define STAGES     3
#define SMEM_TOTAL (STAGES * STAGE_B + 1024)

// ============================================================================
// C[M,N] (fp32) = A[M,Kd] @ B[N,Kd]^T in bf16x3.
// permc >= 0: quaternion-permute A's k-blocks (Anh/Anl used for negated blocks).
// blockIdx.z = batch: A += z*aStrideZ; B rows += z*bOffZ; C cols += z*cOffZ.
// ============================================================================
__global__ void __launch_bounds__(256, 1)
gemm_nt(const __nv_bfloat16* __restrict__ Ah,  const __nv_bfloat16* __restrict__ Al,
        const __nv_bfloat16* __restrict__ Anh, const __nv_bfloat16* __restrict__ Anl,
        const __nv_bfloat16* __restrict__ Bh,  const __nv_bfloat16* __restrict__ Bl,
        float* __restrict__ C,
        int lda, int ldb, int ldc, int Kd, int permc,
        size_t aStrideZ, int bOffZ, int cOffZ)
{
    extern __shared__ char smem_raw[];
    uint32_t sbase = smem_u32(smem_raw);
    sbase = (sbase + 1023u) & ~1023u;

    const int tid  = threadIdx.x;
    const int wid  = tid >> 5;
    const int lane = tid & 31;
    const int z    = blockIdx.z;
    const int m0   = blockIdx.y * 128;
    const int n0   = blockIdx.x * 128;
    const int bRow = n0 + z * bOffZ;
    const int cCol = n0 + z * cOffZ;

    const __nv_bfloat16* Azh = Ah + (size_t)z * aStrideZ;
    const __nv_bfloat16* Azl = Al + (size_t)z * aStrideZ;

    const int nk = Kd >> 6;

    // ---- stage loader: 4 tiles x (128 rows x 128B), swizzle chunk^=(row&7)
    auto issue = [&](int i) {
        int s = i % STAGES;
        uint32_t sb = sbase + (uint32_t)s * STAGE_B;
        int k0 = i << 6;
        const __nv_bfloat16 *pAh = Azh, *pAl = Azl;
        int kA = k0;
        if (permc >= 0) {
            int b = k0 >> 8;
            kA = c_src[permc][b] * 256 + (k0 & 255);
            if (c_neg[permc][b]) { pAh = Anh; pAl = Anl; }
        }
        const __nv_bfloat16* tAh = pAh + (size_t)m0 * lda + kA;
        const __nv_bfloat16* tAl = pAl + (size_t)m0 * lda + kA;
        const __nv_bfloat16* tBh = Bh + (size_t)bRow * ldb + k0;
        const __nv_bfloat16* tBl = Bl + (size_t)bRow * ldb + k0;
        #pragma unroll
        for (int it = 0; it < 4; it++) {
            int id  = tid + 256 * it;
            int row = id >> 3;
            int cc  = id & 7;
            uint32_t d = sb + (uint32_t)(row * 128) + (uint32_t)(((cc ^ (row & 7)) << 4));
            CPASYNC16(d,             (const char*)(tAh + (size_t)row * lda) + cc * 16);
            CPASYNC16(d + TILE_B,    (const char*)(tAl + (size_t)row * lda) + cc * 16);
            CPASYNC16(d + 2*TILE_B,  (const char*)(tBh + (size_t)row * ldb) + cc * 16);
            CPASYNC16(d + 3*TILE_B,  (const char*)(tBl + (size_t)row * ldb) + cc * 16);
        }
        CPCOMMIT();
    };

    issue(0);
    issue(1);

    // ---- per-lane ldmatrix address components
    const int wm = (wid & 3) * 32;     // warp m offset (4 warps over M)
    const int wn = (wid >> 2) * 64;    // warp n offset (2 warps over N)

    int aoff[2], axor[2];
    #pragma unroll
    for (int im = 0; im < 2; im++) {
        int r = wm + im * 16 + (lane & 15);
        aoff[im] = r * 128;
        axor[im] = r & 7;
    }
    const int ach = lane >> 4;               // 0/1 -> k0 / k8 chunk
    int boff[4], bxor[4];
    #pragma unroll
    for (int ng = 0; ng < 4; ng++) {
        int r = wn + ng * 16 + (lane & 7) + ((lane >> 4) & 1) * 8;
        boff[ng] = r * 128;
        bxor[ng] = r & 7;
    }
    const int bch = (lane >> 3) & 1;

    float acc[2][8][4];
    #pragma unroll
    for (int im = 0; im < 2; im++)
        #pragma unroll
        for (int jn = 0; jn < 8; jn++)
            #pragma unroll
            for (int q = 0; q < 4; q++) acc[im][jn][q] = 0.f;

    for (int i = 0; i < nk; i++) {
        if (i + 2 < nk) issue(i + 2); else CPCOMMIT();
        CPWAIT2();
        __syncthreads();

        uint32_t stA = sbase + (uint32_t)(i % STAGES) * STAGE_B;
        uint32_t stB = stA + 2 * TILE_B;

        #pragma unroll
        for (int kk = 0; kk < 4; kk++) {
            uint32_t aH[2][4], aL[2][4], bH[4][4], bL[4][4];
            #pragma unroll
            for (int im = 0; im < 2; im++) {
                uint32_t ad = stA + aoff[im] + (uint32_t)((((kk * 2 + ach) ^ axor[im]) << 4));
                LDSM4(aH[im], ad);
                LDSM4(aL[im], ad + TILE_B);
            }
            #pragma unroll
            for (int ng = 0; ng < 4; ng++) {
                uint32_t bd = stB + boff[ng] + (uint32_t)((((kk * 2 + bch) ^ bxor[ng]) << 4));
                LDSM4(bH[ng], bd);
                LDSM4(bL[ng], bd + TILE_B);
            }
            #pragma unroll
            for (int im = 0; im < 2; im++) {
                #pragma unroll
                for (int jn = 0; jn < 8; jn++) {
                    const int ng = jn >> 1, sub = (jn & 1) * 2;
                    MMA_BF16(acc[im][jn], aH[im], bH[ng][sub], bH[ng][sub + 1]);
                    MMA_BF16(acc[im][jn], aH[im], bL[ng][sub], bL[ng][sub + 1]);
                    MMA_BF16(acc[im][jn], aL[im], bH[ng][sub], bH[ng][sub + 1]);
                }
            }
        }
        __syncthreads();
    }

    // ---- epilogue: direct fp32 stores (2 floats per frag row)
    const int l4 = lane >> 2;
    const int l2 = (lane & 3) * 2;
    #pragma unroll
    for (int im = 0; im < 2; im++) {
        #pragma unroll
        for (int jn = 0; jn < 8; jn++) {
            int r   = m0 + wm + im * 16 + l4;
            int col = cCol + wn + jn * 8 + l2;
            float2 v0 = make_float2(acc[im][jn][0], acc[im][jn][1]);
            float2 v1 = make_float2(acc[im][jn][2], acc[im][jn][3]);
            *(float2*)&C[(size_t)r * ldc + col]       = v0;
            *(float2*)&C[(size_t)(r + 8) * ldc + col] = v1;
        }
    }
}

// ============================================================================
// fp32 -> bf16 hi/lo split kernels
// ============================================================================
__device__ __forceinline__ void split1(float x, __nv_bfloat16& h, __nv_bfloat16& l) {
    h = __float2bfloat16_rn(x);
    l = __float2bfloat16_rn(x - __bfloat162float(h));
}

__global__ void __launch_bounds__(256)
split_hl(const float* __restrict__ in, __nv_bfloat16* __restrict__ h,
         __nv_bfloat16* __restrict__ l, int n4)
{
    int i = blockIdx.x * 256 + threadIdx.x;
    if (i >= n4) return;
    float4 v = ((const float4*)in)[i];
    __nv_bfloat16 h0, h1, h2, h3, l0, l1, l2, l3;
    split1(v.x, h0, l0); split1(v.y, h1, l1); split1(v.z, h2, l2); split1(v.w, h3, l3);
    ((__nv_bfloat162*)h)[i*2]   = __nv_bfloat162(h0, h1);
    ((__nv_bfloat162*)h)[i*2+1] = __nv_bfloat162(h2, h3);
    ((__nv_bfloat162*)l)[i*2]   = __nv_bfloat162(l0, l1);
    ((__nv_bfloat162*)l)[i*2+1] = __nv_bfloat162(l2, l3);
}

__global__ void __launch_bounds__(256)
split_hl_neg(const float* __restrict__ in,
             __nv_bfloat16* __restrict__ h,  __nv_bfloat16* __restrict__ l,
             __nv_bfloat16* __restrict__ nh, __nv_bfloat16* __restrict__ nl, int n4)
{
    int i = blockIdx.x * 256 + threadIdx.x;
    if (i >= n4) return;
    float4 v = ((const float4*)in)[i];
    __nv_bfloat16 h0, h1, h2, h3, l0, l1, l2, l3;
    split1(v.x, h0, l0); split1(v.y, h1, l1); split1(v.z, h2, l2); split1(v.w, h3, l3);
    ((__nv_bfloat162*)h)[i*2]    = __nv_bfloat162(h0, h1);
    ((__nv_bfloat162*)h)[i*2+1]  = __nv_bfloat162(h2, h3);
    ((__nv_bfloat162*)l)[i*2]    = __nv_bfloat162(l0, l1);
    ((__nv_bfloat162*)l)[i*2+1]  = __nv_bfloat162(l2, l3);
    ((__nv_bfloat162*)nh)[i*2]   = __nv_bfloat162(__hneg(h0), __hneg(h1));
    ((__nv_bfloat162*)nh)[i*2+1] = __nv_bfloat162(__hneg(h2), __hneg(h3));
    ((__nv_bfloat162*)nl)[i*2]   = __nv_bfloat162(__hneg(l0), __hneg(l1));
    ((__nv_bfloat162*)nl)[i*2+1] = __nv_bfloat162(__hneg(l2), __hneg(l3));
}

// V[4096,1024] -> Vt hi/lo [1024,4096]
__global__ void __launch_bounds__(1024)
transpose_split(const float* __restrict__ V,
                __nv_bfloat16* __restrict__ Th, __nv_bfloat16* __restrict__ Tl)
{
    __shared__ float t[32][33];
    int bx = blockIdx.x * 32;   // V col
    int by = blockIdx.y * 32;   // V row
    int tx = threadIdx.x, ty = threadIdx.y;
    t[ty][tx] = V[(size_t)(by + ty) * DIM + bx + tx];
    __syncthreads();
    float v = t[tx][ty];
    int orow = bx + ty, ocol = by + tx;
    __nv_bfloat16 h, l; split1(v, h, l);
    Th[(size_t)orow * NSEQ + ocol] = h;
    Tl[(size_t)orow * NSEQ + ocol] = l;
}

// ============================================================================
// Row softmax over 4096 cols; P out as bf16 hi/lo; optional fp32 w mirror.
// ============================================================================
__global__ void __launch_bounds__(256)
softmax_row(const float* __restrict__ L,
            __nv_bfloat16* __restrict__ Ph, __nv_bfloat16* __restrict__ Pl,
            float* __restrict__ wout)
{
    __shared__ float buf[NSEQ];
    __shared__ float red[8];

    const int row = blockIdx.x;
    const float* Lr = L + (size_t)row * NSEQ;
    const int tid = threadIdx.x, lane = tid & 31, wd = tid >> 5;

    float lmax = -3.4e38f;
    #pragma unroll
    for (int it = 0; it < 4; it++) {
        int i = tid * 4 + it * 1024;
        float4 v = *(const float4*)&Lr[i];
        *(float4*)&buf[i] = v;
        lmax = fmaxf(lmax, fmaxf(fmaxf(v.x, v.y), fmaxf(v.z, v.w)));
    }
    #pragma unroll
    for (int o = 16; o; o >>= 1) lmax = fmaxf(lmax, __shfl_xor_sync(0xffffffffu, lmax, o));
    if (lane == 0) red[wd] = lmax;
    __syncthreads();
    if (tid == 0) {
        float m = red[0];
        #pragma unroll
        for (int w = 1; w < 8; w++) m = fmaxf(m, red[w]);
        red[0] = m;
    }
    __syncthreads();
    const float bmax = red[0];
    __syncthreads();

    float lsum = 0.f;
    #pragma unroll
    for (int it = 0; it < 4; it++) {
        int i = tid * 4 + it * 1024;
        float4 v = *(const float4*)&buf[i];
        v.x = __expf(v.x - bmax); v.y = __expf(v.y - bmax);
        v.z = __expf(v.z - bmax); v.w = __expf(v.w - bmax);
        *(float4*)&buf[i] = v;
        lsum += v.x + v.y + v.z + v.w;
    }
    #pragma unroll
    for (int o = 16; o; o >>= 1) lsum += __shfl_xor_sync(0xffffffffu, lsum, o);
    if (lane == 0) red[wd] = lsum;
    __syncthreads();
    if (tid == 0) {
        float s = 0.f;
        #pragma unroll
        for (int w = 0; w < 8; w++) s += red[w];
        red[0] = 1.f / s;
    }
    __syncthreads();
    const float inv = red[0];

    __nv_bfloat16* Hr = Ph + (size_t)row * NSEQ;
    __nv_bfloat16* Lo = Pl + (size_t)row * NSEQ;
    float* Wr = wout ? wout + (size_t)row * NSEQ : nullptr;
    #pragma unroll
    for (int it = 0; it < 4; it++) {
        int i = tid * 4 + it * 1024;
        float4 v = *(const float4*)&buf[i];
        v.x *= inv; v.y *= inv; v.z *= inv; v.w *= inv;
        __nv_bfloat16 h0, h1, h2, h3, l0, l1, l2, l3;
        split1(v.x, h0, l0); split1(v.y, h1, l1); split1(v.z, h2, l2); split1(v.w, h3, l3);
        *(__nv_bfloat162*)&Hr[i]     = __nv_bfloat162(h0, h1);
        *(__nv_bfloat162*)&Hr[i + 2] = __nv_bfloat162(h2, h3);
        *(__nv_bfloat162*)&Lo[i]     = __nv_bfloat162(l0, l1);
        *(__nv_bfloat162*)&Lo[i + 2] = __nv_bfloat162(l2, l3);
        if (Wr) *(float4*)&Wr[i] = v;
    }
}

// ============================================================================
// Host side
// ============================================================================
extern "C" void kernel_launch(void* const* d_in, const int* in_sizes, int n_in,
                              void* d_out, int out_size)
{
    const float* x = (const float*)d_in[0];
    const float* W[3] = { (const float*)d_in[1], (const float*)d_in[2], (const float*)d_in[3] };

    float* yout = (float*)d_out;                 // [4096,1024]
    float* wout = yout + (size_t)NSEQ * DIM;     // [4096,4096]

    float *Qf, *Kf, *Vf, *Lf;
    cudaGetSymbolAddress((void**)&Qf, g_Q);
    cudaGetSymbolAddress((void**)&Kf, g_K);
    cudaGetSymbolAddress((void**)&Vf, g_V);
    cudaGetSymbolAddress((void**)&Lf, g_L);
    __nv_bfloat16 *xh, *xl, *Wh0, *Wl0, *Qh, *Ql, *Qnh, *Qnl, *Kh, *Kl, *Vth, *Vtl, *Ph, *Pl;
    cudaGetSymbolAddress((void**)&xh,  g_xh);  cudaGetSymbolAddress((void**)&xl,  g_xl);
    cudaGetSymbolAddress((void**)&Wh0, g_Wh);  cudaGetSymbolAddress((void**)&Wl0, g_Wl);
    cudaGetSymbolAddress((void**)&Qh,  g_Qh);  cudaGetSymbolAddress((void**)&Ql,  g_Ql);
    cudaGetSymbolAddress((void**)&Qnh, g_Qnh); cudaGetSymbolAddress((void**)&Qnl, g_Qnl);
    cudaGetSymbolAddress((void**)&Kh,  g_Kh);  cudaGetSymbolAddress((void**)&Kl,  g_Kl);
    cudaGetSymbolAddress((void**)&Vth, g_Vth); cudaGetSymbolAddress((void**)&Vtl, g_Vtl);
    cudaGetSymbolAddress((void**)&Ph,  g_Ph);  cudaGetSymbolAddress((void**)&Pl,  g_Pl);

    cudaFuncSetAttribute(gemm_nt, cudaFuncAttributeMaxDynamicSharedMemorySize, SMEM_TOTAL);

    // --- conversions ---
    split_hl<<<NSEQ * DIM / 4 / 256, 256>>>(x, xh, xl, NSEQ * DIM / 4);
    for (int i = 0; i < 3; i++)
        split_hl<<<DIM * DIM / 4 / 256, 256>>>(W[i], Wh0 + (size_t)i * DIM * DIM,
                                               Wl0 + (size_t)i * DIM * DIM, DIM * DIM / 4);

    // --- QKV: [4096,1024] = x @ W^T ---
    float* QKV[3] = { Qf, Kf, Vf };
    for (int i = 0; i < 3; i++)
        gemm_nt<<<dim3(DIM / 128, NSEQ / 128, 1), 256, SMEM_TOTAL>>>(
            xh, xl, xh, xl,
            Wh0 + (size_t)i * DIM * DIM, Wl0 + (size_t)i * DIM * DIM,
            QKV[i], DIM, DIM, DIM, DIM, -1, 0, 0, 0);

    split_hl_neg<<<NSEQ * DIM / 4 / 256, 256>>>(Qf, Qh, Ql, Qnh, Qnl, NSEQ * DIM / 4);
    split_hl<<<NSEQ * DIM / 4 / 256, 256>>>(Kf, Kh, Kl, NSEQ * DIM / 4);
    transpose_split<<<dim3(DIM / 32, NSEQ / 32), dim3(32, 32)>>>(Vf, Vth, Vtl);

    // --- logits + softmax per component ---
    for (int c = 0; c < 4; c++) {
        gemm_nt<<<dim3(NSEQ / 128, NSEQ / 128, 1), 256, SMEM_TOTAL>>>(
            Qh, Ql, Qnh, Qnl, Kh, Kl, Lf, DIM, DIM, NSEQ, DIM, c, 0, 0, 0);
        softmax_row<<<NSEQ, 256>>>(Lf, Ph + (size_t)c * NN, Pl + (size_t)c * NN,
                                   (c == 3) ? wout : nullptr);
    }

    // --- y_c = P_c @ V_c, batched over c via blockIdx.z ---
    gemm_nt<<<dim3(256 / 128, NSEQ / 128, 4), 256, SMEM_TOTAL>>>(
        Ph, Pl, Ph, Pl, Vth, Vtl, yout,
        NSEQ, NSEQ, DIM, NSEQ, -1, NN, 256, 256);
}